// round 4
// baseline (speedup 1.0000x reference)
#include <cuda_runtime.h>
#include <cstdint>

typedef unsigned long long ull;

#define TT 800
#define BB 128
#define HH 256
#define AA 64
#define UU 64
#define KK 10
#define NCTA 128
#define NTHR 256
#define CHUNK 128
#define R1 323
#define R2 579
#define R3 579

// shared layout (floats) for recurrent kernel
#define OFF_W1 0
#define OFF_W2 (R1*32)
#define OFF_W3 (OFF_W2 + R2*32)
#define OFF_BS (OFF_W3 + R3*32)
#define OFF_CS (OFF_BS + 96)
#define OFF_WIN (OFF_CS + 768)
#define OFF_CHR (OFF_WIN + 128)
#define OFF_XS  (OFF_CHR + 64)
#define SMEM_MAIN_FLOATS (OFF_XS + CHUNK*32)
#define SMEM_MAIN_BYTES (SMEM_MAIN_FLOATS*4)   // 210176

#define HEADS_FLOATS (256*128)
#define HEADS_BYTES (HEADS_FLOATS*4)           // 131072

// output layout (floats)
#define OUT_ES 0
#define OUT_PI 102400
#define OUT_M1 (OUT_PI + 2048000)
#define OUT_M2 (OUT_M1 + 2048000)
#define OUT_S1 (OUT_M2 + 2048000)
#define OUT_S2 (OUT_S1 + 2048000)
#define OUT_RH (OUT_S2 + 2048000)

__device__ float g_h1[2*HH*BB];
__device__ float g_h2[2*HH*BB];
__device__ float g_h3[2*HH*BB];
__device__ float g_w[AA*BB];        // [a][b]
__device__ float g_kappa[BB*KK];
__device__ float g_xT[TT*3*BB];     // [t][k][b]
__device__ float g_WwT[30*HH];      // [m][k]
__device__ float g_out[(size_t)TT*HH*BB]; // [t][unit][b]
__device__ unsigned g_bar;

__device__ __forceinline__ float sig_(float x){ return 1.0f/(1.0f+__expf(-x)); }

__device__ __forceinline__ void gridbar(unsigned target){
    // release: every thread fences its own global stores before arrival
    __threadfence();
    __syncthreads();
    if (threadIdx.x == 0){
        atomicAdd(&g_bar, 1u);
        while (*(volatile unsigned*)&g_bar < target) { }
    }
    __syncthreads();
    __threadfence();
}

__device__ __forceinline__ float fetch_in(int gk, int b, int bt32,
                                          const float* xrow,
                                          const float* hA, const float* hB){
    if (gk < 3)   return __ldcg(xrow + gk*BB + bt32 + b);
    if (gk < 67)  return __ldcg(g_w + (gk-3)*BB + bt32 + b);
    if (gk < 323) return __ldcg(hA + (gk-67)*BB + bt32 + b);
    return __ldcg(hB + (gk-323)*BB + bt32 + b);
}

__device__ __forceinline__ ull rep2(float v){
    ull r; asm("mov.b64 %0, {%1, %1};" : "=l"(r) : "f"(v)); return r;
}
__device__ __forceinline__ void fma2(ull& acc, ull a, ull b){
    asm("fma.rn.f32x2 %0, %1, %2, %0;" : "+l"(acc) : "l"(a), "l"(b));
}
__device__ __forceinline__ float2 unpk(ull v){
    float2 r; asm("mov.b64 {%0, %1}, %2;" : "=f"(r.x), "=f"(r.y) : "l"(v)); return r;
}

// One LSTM gate-GEMM + cell update for this CTA's 32 batches x 32 gate-cols.
__device__ __forceinline__ void lstm_phase(
    float* sm, const float* Wsm, const float* bsl, float* cstl,
    int rows, const float* xrow, const float* hA, const float* hB,
    float* hOut, float* outRow, int bt32, int ht)
{
    const int tid = threadIdx.x;
    float* Xs = sm + OFF_XS;
    const int kg = tid >> 7;          // k-split group
    const int g  = tid & 127;
    const int c2 = (g & 15)*2;        // col pair
    const int bq = (g >> 4)*4;        // batch quad

    ull a00=0, a01=0, a10=0, a11=0;   // [col][batch-pair]
    float rbuf[16];

    #pragma unroll
    for (int i = 0; i < 16; i++){
        int idx = tid + i*256;
        int gk = idx >> 5, b = idx & 31;
        rbuf[i] = (gk < rows) ? fetch_in(gk, b, bt32, xrow, hA, hB) : 0.f;
    }

    for (int k0 = 0; k0 < rows; k0 += CHUNK){
        __syncthreads();
        #pragma unroll
        for (int i = 0; i < 16; i++) Xs[tid + i*256] = rbuf[i];
        __syncthreads();
        int nk0 = k0 + CHUNK;
        if (nk0 < rows){
            #pragma unroll
            for (int i = 0; i < 16; i++){
                int idx = tid + i*256;
                int gk = nk0 + (idx >> 5), b = idx & 31;
                rbuf[i] = (gk < rows) ? fetch_in(gk, b, bt32, xrow, hA, hB) : 0.f;
            }
        }
        int kn = rows - k0; if (kn > CHUNK) kn = CHUNK;
        if (kn == CHUNK){
            const float* xp = Xs + (kg*64)*32 + bq;
            const float* wp = Wsm + (k0 + kg*64)*32 + c2;
            #pragma unroll 8
            for (int kk = 0; kk < 64; kk++){
                longlong2 xv = *(const longlong2*)xp;
                float2 wv = *(const float2*)wp;
                ull wx = rep2(wv.x), wy = rep2(wv.y);
                fma2(a00, (ull)xv.x, wx); fma2(a01, (ull)xv.y, wx);
                fma2(a10, (ull)xv.x, wy); fma2(a11, (ull)xv.y, wy);
                xp += 32; wp += 32;
            }
        } else {
            int kh = kn >> 1;
            int ks = kg ? kh : 0, ke = kg ? kn : kh;
            for (int kk = ks; kk < ke; kk++){
                longlong2 xv = *(const longlong2*)(Xs + kk*32 + bq);
                float2 wv = *(const float2*)(Wsm + (k0+kk)*32 + c2);
                ull wx = rep2(wv.x), wy = rep2(wv.y);
                fma2(a00, (ull)xv.x, wx); fma2(a01, (ull)xv.y, wx);
                fma2(a10, (ull)xv.x, wy); fma2(a11, (ull)xv.y, wy);
            }
        }
    }
    __syncthreads();
    // reduce k-split partials via smem (reuse Xs)
    {
        float2 v00 = unpk(a00), v01 = unpk(a01), v10 = unpk(a10), v11 = unpk(a11);
        if (kg == 0){
            *(float2*)(Xs + (c2  )*32 + bq    ) = v00;
            *(float2*)(Xs + (c2  )*32 + bq + 2) = v01;
            *(float2*)(Xs + (c2+1)*32 + bq    ) = v10;
            *(float2*)(Xs + (c2+1)*32 + bq + 2) = v11;
        }
        __syncthreads();
        if (kg == 1){
            float2* p0 = (float2*)(Xs + (c2  )*32 + bq);
            float2* p1 = (float2*)(Xs + (c2  )*32 + bq + 2);
            float2* p2 = (float2*)(Xs + (c2+1)*32 + bq);
            float2* p3 = (float2*)(Xs + (c2+1)*32 + bq + 2);
            float2 t0=*p0, t1=*p1, t2=*p2, t3=*p3;
            t0.x+=v00.x; t0.y+=v00.y; t1.x+=v01.x; t1.y+=v01.y;
            t2.x+=v10.x; t2.y+=v10.y; t3.x+=v11.x; t3.y+=v11.y;
            *p0=t0; *p1=t1; *p2=t2; *p3=t3;
        }
        __syncthreads();
    }
    // cell update: tid -> (unit u, batch b)
    const int b = tid & 31, u = tid >> 5;
    float iv = Xs[(u)     *32 + b] + bsl[u];
    float fv = Xs[(8 + u) *32 + b] + bsl[8 + u];
    float gv = Xs[(16 + u)*32 + b] + bsl[16 + u];
    float ov = Xs[(24 + u)*32 + b] + bsl[24 + u];
    float ival = sig_(iv), fval = sig_(fv), gval = tanhf(gv), oval = sig_(ov);
    float cnew = fmaf(fval, cstl[tid], ival*gval);
    cstl[tid] = cnew;
    float h = oval * tanhf(cnew);
    int gidx = (ht*8 + u)*BB + bt32 + b;
    __stcg(hOut + gidx, h);
    if (outRow) outRow[gidx] = h;
}

__device__ __forceinline__ void window_phase(float* sm, const float* bw,
                                             const float* h1new, int wb){
    const int tid = threadIdx.x;
    float* winb = sm + OFF_WIN;
    const int* chars = (const int*)(sm + OFF_CHR);
    const int lane = tid & 31, wr = tid >> 5;

    float vr0=0.f, vr1=0.f, vr2=0.f, vr3=0.f;
    #pragma unroll
    for (int kk = 0; kk < 8; kk++){
        int k = kk*32 + lane;
        float hv = __ldcg(h1new + k*BB + wb);
        vr0 = fmaf(hv, g_WwT[(wr)    *HH + k], vr0);
        vr1 = fmaf(hv, g_WwT[(wr+8)  *HH + k], vr1);
        vr2 = fmaf(hv, g_WwT[(wr+16) *HH + k], vr2);
        if (wr < 6) vr3 = fmaf(hv, g_WwT[(wr+24)*HH + k], vr3);
    }
    #pragma unroll
    for (int off = 16; off; off >>= 1){
        vr0 += __shfl_down_sync(0xffffffffu, vr0, off);
        vr1 += __shfl_down_sync(0xffffffffu, vr1, off);
        vr2 += __shfl_down_sync(0xffffffffu, vr2, off);
        vr3 += __shfl_down_sync(0xffffffffu, vr3, off);
    }
    if (lane == 0){
        winb[wr] = vr0; winb[wr+8] = vr1; winb[wr+16] = vr2;
        if (wr < 6) winb[wr+24] = vr3;
    }
    __syncthreads();
    if (tid < 30){
        float e = __expf(winb[tid] + bw[tid]);
        if (tid >= 20){
            float kap = fmaf(0.1f, e, g_kappa[wb*KK + tid - 20]);
            g_kappa[wb*KK + tid - 20] = kap;
            e = kap;
        }
        winb[32 + tid] = e;
    }
    if (tid >= 64 && tid < 128) winb[tid] = 0.f;
    __syncthreads();
    if (tid < 64){
        float fu = (float)tid;
        float s = 0.f;
        #pragma unroll
        for (int k = 0; k < KK; k++){
            float d = winb[52 + k] - fu;
            s = fmaf(winb[32 + k], __expf(-winb[42 + k]*d*d), s);
        }
        atomicAdd(winb + 64 + chars[tid], s);
    }
    __syncthreads();
    if (tid < 64) __stcg(g_w + tid*BB + wb, winb[64 + tid]);
}

__global__ void __launch_bounds__(NTHR, 1) recurrent_kernel(
    const int* __restrict__ c,
    const float* __restrict__ Wih1, const float* __restrict__ Whh1,
    const float* __restrict__ bih1, const float* __restrict__ bhh1,
    const float* __restrict__ Wih2, const float* __restrict__ Whh2,
    const float* __restrict__ bih2, const float* __restrict__ bhh2,
    const float* __restrict__ Wih3, const float* __restrict__ Whh3,
    const float* __restrict__ bih3, const float* __restrict__ bhh3,
    const float* __restrict__ bw)
{
    extern __shared__ float sm[];
    const int tid = threadIdx.x;
    const int bx = blockIdx.x;
    const int bt = bx >> 5, ht = bx & 31;
    const int bt32 = bt*32;

    for (int idx = tid; idx < R1*32; idx += NTHR){
        int k = idx >> 5, cc = idx & 31;
        int j = (cc >> 3)*256 + ht*8 + (cc & 7);
        sm[OFF_W1 + idx] = (k < 67) ? Wih1[k*1024 + j] : Whh1[(k-67)*1024 + j];
    }
    for (int idx = tid; idx < R2*32; idx += NTHR){
        int k = idx >> 5, cc = idx & 31;
        int j = (cc >> 3)*256 + ht*8 + (cc & 7);
        sm[OFF_W2 + idx] = (k < 323) ? Wih2[k*1024 + j] : Whh2[(k-323)*1024 + j];
    }
    for (int idx = tid; idx < R3*32; idx += NTHR){
        int k = idx >> 5, cc = idx & 31;
        int j = (cc >> 3)*256 + ht*8 + (cc & 7);
        sm[OFF_W3 + idx] = (k < 323) ? Wih3[k*1024 + j] : Whh3[(k-323)*1024 + j];
    }
    if (tid < 96){
        int l = tid >> 5, cc = tid & 31;
        int j = (cc >> 3)*256 + ht*8 + (cc & 7);
        const float* bi = (l == 0) ? bih1 : ((l == 1) ? bih2 : bih3);
        const float* bh = (l == 0) ? bhh1 : ((l == 1) ? bhh2 : bhh3);
        sm[OFF_BS + tid] = bi[j] + bh[j];
    }
    for (int i = tid; i < 768; i += NTHR) sm[OFF_CS + i] = 0.f;
    if (tid < 64) ((int*)(sm + OFF_CHR))[tid] = c[bx*UU + tid];
    __syncthreads();

    int rp = 0;
    unsigned bar_target = 0;
    for (int t = 0; t < TT; t++){
        const float* xrow = g_xT + t*3*BB;
        const int wp = rp ^ 1;

        lstm_phase(sm, sm + OFF_W1, sm + OFF_BS, sm + OFF_CS, R1,
                   xrow, g_h1 + rp*(HH*BB), g_h1 + rp*(HH*BB),
                   g_h1 + wp*(HH*BB), nullptr, bt32, ht);
        bar_target += NCTA; gridbar(bar_target);

        window_phase(sm, bw, g_h1 + wp*(HH*BB), bx);
        bar_target += NCTA; gridbar(bar_target);

        lstm_phase(sm, sm + OFF_W2, sm + OFF_BS + 32, sm + OFF_CS + 256, R2,
                   xrow, g_h1 + wp*(HH*BB), g_h2 + rp*(HH*BB),
                   g_h2 + wp*(HH*BB), nullptr, bt32, ht);
        bar_target += NCTA; gridbar(bar_target);

        lstm_phase(sm, sm + OFF_W3, sm + OFF_BS + 64, sm + OFF_CS + 512, R3,
                   xrow, g_h2 + wp*(HH*BB), g_h3 + rp*(HH*BB),
                   g_h3 + wp*(HH*BB), g_out + (size_t)t*HH*BB, bt32, ht);
        rp = wp;
    }
}

__global__ void __launch_bounds__(256) heads_kernel(
    const float* __restrict__ We, const float* __restrict__ be,
    const float* __restrict__ Wpi, const float* __restrict__ bpi,
    const float* __restrict__ Wmu1, const float* __restrict__ bmu1,
    const float* __restrict__ Wmu2, const float* __restrict__ bmu2,
    const float* __restrict__ Ws1, const float* __restrict__ bs1,
    const float* __restrict__ Ws2, const float* __restrict__ bs2,
    const float* __restrict__ Wrho, const float* __restrict__ brho,
    float* __restrict__ dout)
{
    extern __shared__ float ws[];   // [256 k][128 j], reused as gates [128 j][128 b]
    const int tid = threadIdx.x;
    const int t = blockIdx.x;

    for (int idx = tid; idx < 256*128; idx += 256){
        int k = idx >> 7, j = idx & 127;
        float v = 0.f;
        if (j == 0)       v = We[k];
        else if (j < 21)  v = Wpi [k*20 + j-1];
        else if (j < 41)  v = Wmu1[k*20 + j-21];
        else if (j < 61)  v = Wmu2[k*20 + j-41];
        else if (j < 81)  v = Ws1 [k*20 + j-61];
        else if (j < 101) v = Ws2 [k*20 + j-81];
        else if (j < 121) v = Wrho[k*20 + j-101];
        ws[idx] = v;
    }
    __syncthreads();

    const int bg = tid & 31, jg = tid >> 5;      // 32 batch-quads x 8 j-groups(16)
    const float* hsrc = g_out + (size_t)t*HH*BB;
    float acc[64];
    #pragma unroll
    for (int i = 0; i < 64; i++) acc[i] = 0.f;

    for (int k = 0; k < 256; k++){
        float4 hv = *(const float4*)(hsrc + k*128 + bg*4);
        #pragma unroll
        for (int jj = 0; jj < 16; jj += 4){
            float4 wv = *(const float4*)(ws + k*128 + jg*16 + jj);
            acc[(jj+0)*4+0] = fmaf(hv.x, wv.x, acc[(jj+0)*4+0]);
            acc[(jj+0)*4+1] = fmaf(hv.y, wv.x, acc[(jj+0)*4+1]);
            acc[(jj+0)*4+2] = fmaf(hv.z, wv.x, acc[(jj+0)*4+2]);
            acc[(jj+0)*4+3] = fmaf(hv.w, wv.x, acc[(jj+0)*4+3]);
            acc[(jj+1)*4+0] = fmaf(hv.x, wv.y, acc[(jj+1)*4+0]);
            acc[(jj+1)*4+1] = fmaf(hv.y, wv.y, acc[(jj+1)*4+1]);
            acc[(jj+1)*4+2] = fmaf(hv.z, wv.y, acc[(jj+1)*4+2]);
            acc[(jj+1)*4+3] = fmaf(hv.w, wv.y, acc[(jj+1)*4+3]);
            acc[(jj+2)*4+0] = fmaf(hv.x, wv.z, acc[(jj+2)*4+0]);
            acc[(jj+2)*4+1] = fmaf(hv.y, wv.z, acc[(jj+2)*4+1]);
            acc[(jj+2)*4+2] = fmaf(hv.z, wv.z, acc[(jj+2)*4+2]);
            acc[(jj+2)*4+3] = fmaf(hv.w, wv.z, acc[(jj+2)*4+3]);
            acc[(jj+3)*4+0] = fmaf(hv.x, wv.w, acc[(jj+3)*4+0]);
            acc[(jj+3)*4+1] = fmaf(hv.y, wv.w, acc[(jj+3)*4+1]);
            acc[(jj+3)*4+2] = fmaf(hv.z, wv.w, acc[(jj+3)*4+2]);
            acc[(jj+3)*4+3] = fmaf(hv.w, wv.w, acc[(jj+3)*4+3]);
        }
    }
    __syncthreads();
    #pragma unroll
    for (int jj = 0; jj < 16; jj++)
        #pragma unroll
        for (int bb = 0; bb < 4; bb++)
            ws[(jg*16 + jj)*128 + bg*4 + bb] = acc[jj*4 + bb];
    __syncthreads();

    if (tid < 128){
        const int b = tid;
        const int tb = t*128 + b;
        float ve = ws[b] + be[0];
        dout[OUT_ES + tb] = 1.0f/(1.0f + __expf(ve));
        float pv[20]; float m = -1e30f;
        #pragma unroll
        for (int g = 0; g < 20; g++){
            pv[g] = ws[(1+g)*128 + b] + bpi[g];
            m = fmaxf(m, pv[g]);
        }
        float s = 0.f;
        #pragma unroll
        for (int g = 0; g < 20; g++){ pv[g] = __expf(pv[g] - m); s += pv[g]; }
        float inv = 1.0f/s;
        #pragma unroll
        for (int g = 0; g < 20; g++){
            dout[OUT_PI + tb*20 + g] = pv[g]*inv;
            dout[OUT_M1 + tb*20 + g] = ws[(21+g) *128 + b] + bmu1[g];
            dout[OUT_M2 + tb*20 + g] = ws[(41+g) *128 + b] + bmu2[g];
            dout[OUT_S1 + tb*20 + g] = __expf(ws[(61+g)*128 + b] + bs1[g]);
            dout[OUT_S2 + tb*20 + g] = __expf(ws[(81+g)*128 + b] + bs2[g]);
            dout[OUT_RH + tb*20 + g] = tanhf(ws[(101+g)*128 + b] + brho[g]);
        }
    }
}

__global__ void prep_kernel(const float* __restrict__ x, const float* __restrict__ Ww){
    int i = blockIdx.x*blockDim.x + threadIdx.x;
    if (i == 0) g_bar = 0u;
    if (i < TT*3*BB){
        int t = i / 384; int r = i - t*384; int k = r >> 7; int b = r & 127;
        g_xT[i] = x[b*(TT*3) + t*3 + k];
    }
    if (i < 30*HH){ int m = i >> 8, k = i & 255; g_WwT[i] = Ww[k*30 + m]; }
    if (i < 2*HH*BB){ g_h1[i] = 0.f; g_h2[i] = 0.f; g_h3[i] = 0.f; }
    if (i < AA*BB) g_w[i] = 1.0f;
    if (i < BB*KK) g_kappa[i] = 0.f;
}

extern "C" void kernel_launch(void* const* d_in, const int* in_sizes, int n_in,
                              void* d_out, int out_size){
    const float* x    = (const float*)d_in[0];
    const int*   c    = (const int*)  d_in[1];
    const float* Wih1 = (const float*)d_in[2];
    const float* Whh1 = (const float*)d_in[3];
    const float* bih1 = (const float*)d_in[4];
    const float* bhh1 = (const float*)d_in[5];
    const float* Wih2 = (const float*)d_in[6];
    const float* Whh2 = (const float*)d_in[7];
    const float* bih2 = (const float*)d_in[8];
    const float* bhh2 = (const float*)d_in[9];
    const float* Wih3 = (const float*)d_in[10];
    const float* Whh3 = (const float*)d_in[11];
    const float* bih3 = (const float*)d_in[12];
    const float* bhh3 = (const float*)d_in[13];
    const float* Ww   = (const float*)d_in[14];
    const float* bw   = (const float*)d_in[15];
    const float* We   = (const float*)d_in[16];
    const float* be   = (const float*)d_in[17];
    const float* Wpi  = (const float*)d_in[18];
    const float* bpi  = (const float*)d_in[19];
    const float* Wmu1 = (const float*)d_in[20];
    const float* bmu1 = (const float*)d_in[21];
    const float* Wmu2 = (const float*)d_in[22];
    const float* bmu2 = (const float*)d_in[23];
    const float* Ws1  = (const float*)d_in[24];
    const float* bs1  = (const float*)d_in[25];
    const float* Ws2  = (const float*)d_in[26];
    const float* bs2  = (const float*)d_in[27];
    const float* Wrho = (const float*)d_in[28];
    const float* brho = (const float*)d_in[29];
    float* dout = (float*)d_out;

    cudaFuncSetAttribute(recurrent_kernel,
        cudaFuncAttributeMaxDynamicSharedMemorySize, SMEM_MAIN_BYTES);
    cudaFuncSetAttribute(heads_kernel,
        cudaFuncAttributeMaxDynamicSharedMemorySize, HEADS_BYTES);

    prep_kernel<<<1200, 256>>>(x, Ww);
    recurrent_kernel<<<NCTA, NTHR, SMEM_MAIN_BYTES>>>(
        c, Wih1, Whh1, bih1, bhh1, Wih2, Whh2, bih2, bhh2,
        Wih3, Whh3, bih3, bhh3, bw);
    heads_kernel<<<TT, 256, HEADS_BYTES>>>(
        We, be, Wpi, bpi, Wmu1, bmu1, Wmu2, bmu2,
        Ws1, bs1, Ws2, bs2, Wrho, brho, dout);
}